// round 3
// baseline (speedup 1.0000x reference)
#include <cuda_runtime.h>
#include <math.h>
#include <mma.h>

using namespace nvcuda;

#define NN    50000
#define EE    400000
#define HH    128
#define NRBFN 20
#define NOUT  384          // 3*H
#define FCUT  8.0f
#define NT    4096         // distance table resolution

// Scratch (device globals: allocation-free rule)
__device__ float g_spn[NN * NOUT];    // per-node scalar-MLP output, 76.8 MB
__device__ float g_tab[NT * NOUT];    // W(d) table, 6.3 MB (L2-resident)
__device__ int   g_rowptr[NN + 1];    // dst-CSR row pointers
__device__ int   g_woff[NN];          // scatter cursors
__device__ int   g_perm[EE];          // edge ids grouped by dst

__device__ __forceinline__ float silu_f(float x) {
    return x / (1.0f + __expf(-x));
}

// ---------------------------------------------------------------------------
// CSR build: zero -> histogram(dst) -> scan -> scatter
// ---------------------------------------------------------------------------
__global__ void zero_cnt_kernel() {
    int i = blockIdx.x * blockDim.x + threadIdx.x;
    if (i <= NN) g_rowptr[i] = 0;
}

__global__ void hist_kernel(const int* __restrict__ ei) {
    int e = blockIdx.x * blockDim.x + threadIdx.x;
    if (e < EE) atomicAdd(&g_rowptr[ei[EE + e] + 1], 1);
}

// single block, 1024 threads; inclusive scan of g_rowptr[0..NN]
__global__ void scan_kernel() {
    const int NTOT = NN + 1;
    const int C = (NTOT + 1023) / 1024;   // 49
    __shared__ int sums[1024];
    int t = threadIdx.x;
    int base = t * C;
    int s = 0;
    for (int i = 0; i < C; i++) {
        int idx = base + i;
        if (idx < NTOT) s += g_rowptr[idx];
    }
    sums[t] = s;
    __syncthreads();
    // Hillis-Steele inclusive scan
    for (int off = 1; off < 1024; off <<= 1) {
        int v = (t >= off) ? sums[t - off] : 0;
        __syncthreads();
        sums[t] += v;
        __syncthreads();
    }
    int run = (t == 0) ? 0 : sums[t - 1];   // exclusive prefix of this chunk
    for (int i = 0; i < C; i++) {
        int idx = base + i;
        if (idx < NTOT) {
            run += g_rowptr[idx];
            g_rowptr[idx] = run;             // inclusive
            if (idx < NN) g_woff[idx] = run; // final rowptr[idx] (start of group idx)
        }
    }
}

__global__ void scatter_kernel(const int* __restrict__ ei) {
    int e = blockIdx.x * blockDim.x + threadIdx.x;
    if (e < EE) {
        int dst = ei[EE + e];
        int p = atomicAdd(&g_woff[dst], 1);
        g_perm[p] = e;
    }
}

// ---------------------------------------------------------------------------
// W(d) table. 8 rows per block, 128 threads.
// ---------------------------------------------------------------------------
__global__ void build_tab_kernel(const float* __restrict__ rbf_c,
                                 const float* __restrict__ rbf_w,
                                 const float* __restrict__ w1,   // [128,20]
                                 const float* __restrict__ b1,   // [128]
                                 const float* __restrict__ w2,   // [384,128]
                                 const float* __restrict__ b2) { // [384]
    __shared__ float feat_sm[8][NRBFN];
    __shared__ float g_sm[8][HH];
    const int tid  = threadIdx.x;        // 128
    const int row0 = blockIdx.x * 8;

    for (int idx = tid; idx < 8 * NRBFN; idx += 128) {
        int r = idx / NRBFN, i = idx % NRBFN;
        float d   = (row0 + r) * (FCUT / (float)(NT - 1));
        float x   = d / FCUT;
        float env = (x < 1.0f) ? 0.5f * (__cosf(3.14159265358979f * x) + 1.0f) : 0.0f;
        float df  = d - rbf_c[i];
        feat_sm[r][i] = __expf(-fabsf(rbf_w[i]) * df * df) * env;
    }
    __syncthreads();

    float wrow[NRBFN];
    #pragma unroll
    for (int i = 0; i < NRBFN; i++) wrow[i] = w1[tid * NRBFN + i];
    float bb = b1[tid];
    #pragma unroll
    for (int r = 0; r < 8; r++) {
        float a = bb;
        #pragma unroll
        for (int i = 0; i < NRBFN; i++) a += feat_sm[r][i] * wrow[i];
        g_sm[r][tid] = silu_f(a);
    }
    __syncthreads();

    float a0[8], a1[8], a2[8];
    #pragma unroll
    for (int r = 0; r < 8; r++) { a0[r] = 0.f; a1[r] = 0.f; a2[r] = 0.f; }
    const float* w2r0 = w2 + (tid)       * HH;
    const float* w2r1 = w2 + (tid + 128) * HH;
    const float* w2r2 = w2 + (tid + 256) * HH;
    for (int k = 0; k < HH; k++) {
        float x0 = w2r0[k], x1 = w2r1[k], x2 = w2r2[k];
        #pragma unroll
        for (int r = 0; r < 8; r++) {
            float h = g_sm[r][k];
            a0[r] += h * x0; a1[r] += h * x1; a2[r] += h * x2;
        }
    }
    float c0 = b2[tid], c1 = b2[tid + 128], c2 = b2[tid + 256];
    #pragma unroll
    for (int r = 0; r < 8; r++) {
        float* o = g_tab + (row0 + r) * NOUT;
        o[tid]       = a0[r] + c0;
        o[tid + 128] = a1[r] + c1;
        o[tid + 256] = a2[r] + c2;
    }
}

// ---------------------------------------------------------------------------
// Node scalar MLP with tf32 WMMA tensor cores.
// Block: 256 threads (8 warps), 64 rows per block.
// smem: s_sm[64*128] | h_sm[64*128] | w_sm[128*128] | out_sm[64*96]
// ---------------------------------------------------------------------------
#define MLP_SMEM_FLOATS (64*128 + 64*128 + 128*128 + 64*96)

__global__ void node_mlp_wmma(const float* __restrict__ s,
                              const float* __restrict__ w1,   // [128,128]
                              const float* __restrict__ b1,
                              const float* __restrict__ w2,   // [384,128]
                              const float* __restrict__ b2) {
    extern __shared__ float sm[];
    float* s_sm   = sm;                    // 8192
    float* h_sm   = sm + 8192;             // 8192
    float* w_sm   = sm + 16384;            // 16384 (layer1) / 12288 (layer2 chunk)
    float* out_sm = sm + 32768;            // 6144

    const int tid  = threadIdx.x;          // 256
    const int warp = tid >> 5;             // 8 warps
    const int n0   = blockIdx.x * 64;

    // load s tile (clamp OOB rows)
    {
        const float4* s4 = (const float4*)s;
        float4* d4 = (float4*)s_sm;
        for (int q = tid; q < 64 * 32; q += 256) {
            int r  = q >> 5;
            int gr = n0 + r; if (gr >= NN) gr = NN - 1;
            d4[q] = s4[gr * 32 + (q & 31)];
        }
    }
    // load W1
    {
        const float4* w4 = (const float4*)w1;
        float4* d4 = (float4*)w_sm;
        for (int q = tid; q < 128 * 32; q += 256) d4[q] = w4[q];
    }
    __syncthreads();

    // ---- layer 1: h = s @ W1^T ----
    {
        const int mt    = warp >> 1;           // 0..3
        const int nhalf = warp & 1;            // 0..1
        wmma::fragment<wmma::accumulator, 16, 16, 8, float> c[4];
        #pragma unroll
        for (int j = 0; j < 4; j++) wmma::fill_fragment(c[j], 0.0f);
        for (int k = 0; k < HH; k += 8) {
            wmma::fragment<wmma::matrix_a, 16, 16, 8, wmma::precision::tf32, wmma::row_major> a;
            wmma::load_matrix_sync(a, s_sm + mt * 16 * 128 + k, 128);
            #pragma unroll
            for (int i = 0; i < a.num_elements; i++) a.x[i] = wmma::__float_to_tf32(a.x[i]);
            #pragma unroll
            for (int j = 0; j < 4; j++) {
                wmma::fragment<wmma::matrix_b, 16, 16, 8, wmma::precision::tf32, wmma::col_major> b;
                wmma::load_matrix_sync(b, w_sm + (nhalf * 64 + j * 16) * 128 + k, 128);
                #pragma unroll
                for (int i = 0; i < b.num_elements; i++) b.x[i] = wmma::__float_to_tf32(b.x[i]);
                wmma::mma_sync(c[j], a, b, c[j]);
            }
        }
        #pragma unroll
        for (int j = 0; j < 4; j++)
            wmma::store_matrix_sync(h_sm + mt * 16 * 128 + (nhalf * 64 + j * 16), c[j], 128,
                                    wmma::mem_row_major);
    }
    __syncthreads();
    // bias + silu
    for (int i = tid; i < 64 * 128; i += 256)
        h_sm[i] = silu_f(h_sm[i] + b1[i & 127]);
    __syncthreads();

    // ---- layer 2: sp = h @ W2^T, in 4 chunks of 96 output cols ----
    for (int chunk = 0; chunk < 4; chunk++) {
        // load W2 chunk [96 x 128]
        {
            const float4* w4 = (const float4*)(w2 + chunk * 96 * 128);
            float4* d4 = (float4*)w_sm;
            for (int q = tid; q < 96 * 32; q += 256) d4[q] = w4[q];
        }
        __syncthreads();

        const int mt = warp >> 1;
        const int nh = warp & 1;               // 3 n-tiles each
        wmma::fragment<wmma::accumulator, 16, 16, 8, float> c[3];
        #pragma unroll
        for (int j = 0; j < 3; j++) wmma::fill_fragment(c[j], 0.0f);
        for (int k = 0; k < HH; k += 8) {
            wmma::fragment<wmma::matrix_a, 16, 16, 8, wmma::precision::tf32, wmma::row_major> a;
            wmma::load_matrix_sync(a, h_sm + mt * 16 * 128 + k, 128);
            #pragma unroll
            for (int i = 0; i < a.num_elements; i++) a.x[i] = wmma::__float_to_tf32(a.x[i]);
            #pragma unroll
            for (int j = 0; j < 3; j++) {
                wmma::fragment<wmma::matrix_b, 16, 16, 8, wmma::precision::tf32, wmma::col_major> b;
                wmma::load_matrix_sync(b, w_sm + (nh * 48 + j * 16) * 128 + k, 128);
                #pragma unroll
                for (int i = 0; i < b.num_elements; i++) b.x[i] = wmma::__float_to_tf32(b.x[i]);
                wmma::mma_sync(c[j], a, b, c[j]);
            }
        }
        #pragma unroll
        for (int j = 0; j < 3; j++)
            wmma::store_matrix_sync(out_sm + mt * 16 * 96 + (nh * 48 + j * 16), c[j], 96,
                                    wmma::mem_row_major);
        __syncthreads();

        // bias + write g_spn
        for (int i = tid; i < 64 * 96; i += 256) {
            int r = i / 96, n = i - r * 96;
            int gr = n0 + r;
            if (gr < NN)
                g_spn[gr * NOUT + chunk * 96 + n] = out_sm[i] + b2[chunk * 96 + n];
        }
        __syncthreads();
    }
}

// ---------------------------------------------------------------------------
// Edge accumulate: one warp per DST node; no atomics, init fused.
// Lane l owns h = 4l..4l+3 (contiguous float4 lanes).
// ---------------------------------------------------------------------------
__global__ void accum_kernel(const float* __restrict__ pos,
                             const float* __restrict__ s,
                             const float* __restrict__ v,
                             const int* __restrict__ ei,
                             float* __restrict__ out) {
    const int gw   = (blockIdx.x * blockDim.x + threadIdx.x) >> 5;
    const int lane = threadIdx.x & 31;
    if (gw >= NN) return;
    const int dst = gw;

    // accumulators initialized from s[dst], v[dst]
    float4 accS = ((const float4*)(s + (size_t)dst * HH))[lane];
    const float4* vrow_d = (const float4*)(v + (size_t)dst * NOUT);
    float4 av0 = vrow_d[3 * lane + 0];
    float4 av1 = vrow_d[3 * lane + 1];
    float4 av2 = vrow_d[3 * lane + 2];

    const int beg = g_rowptr[dst];
    const int end = g_rowptr[dst + 1];

    const float pdx = pos[dst * 3 + 0];
    const float pdy = pos[dst * 3 + 1];
    const float pdz = pos[dst * 3 + 2];

    for (int base = beg; base < end; base += 32) {
        const int cnt = min(32, end - base);
        int   srcE = 0, i0E = 0;
        float fE = 0.f, uxE = 0.f, uyE = 0.f, uzE = 0.f;
        const int mye = base + lane;
        if (mye < end) {
            int e = g_perm[mye];
            srcE = ei[e];
            float rx = pdx - pos[srcE * 3 + 0];
            float ry = pdy - pos[srcE * 3 + 1];
            float rz = pdz - pos[srcE * 3 + 2];
            float d  = fmaxf(sqrtf(rx * rx + ry * ry + rz * rz), 1e-6f);
            float iv = 1.0f / d;
            uxE = rx * iv; uyE = ry * iv; uzE = rz * iv;
            float t = fminf(d, FCUT) * ((float)(NT - 1) / FCUT);
            i0E = (int)t;
            if (i0E > NT - 2) i0E = NT - 2;
            fE = t - (float)i0E;
        }
        for (int t = 0; t < cnt; t++) {
            const int   srcT = __shfl_sync(0xffffffffu, srcE, t);
            const int   i0T  = __shfl_sync(0xffffffffu, i0E, t);
            const float fT   = __shfl_sync(0xffffffffu, fE, t);
            const float uxT  = __shfl_sync(0xffffffffu, uxE, t);
            const float uyT  = __shfl_sync(0xffffffffu, uyE, t);
            const float uzT  = __shfl_sync(0xffffffffu, uzE, t);

            const float4* tb0 = (const float4*)(g_tab + (size_t)i0T * NOUT);
            const float4* tb1 = tb0 + 96;
            const float4* spr = (const float4*)(g_spn + (size_t)srcT * NOUT);
            const float4* vr  = (const float4*)(v + (size_t)srcT * NOUT);

            float4 t0a = tb0[lane], t0b = tb0[32 + lane], t0c = tb0[64 + lane];
            float4 t1a = tb1[lane], t1b = tb1[32 + lane], t1c = tb1[64 + lane];
            float4 spa = spr[lane], spb = spr[32 + lane], spc = spr[64 + lane];
            float4 va  = vr[3 * lane + 0];
            float4 vb  = vr[3 * lane + 1];
            float4 vc  = vr[3 * lane + 2];

            // lerp weights
            float4 wS, w1v, w2v;
            wS.x  = fmaf(fT, t1a.x - t0a.x, t0a.x);
            wS.y  = fmaf(fT, t1a.y - t0a.y, t0a.y);
            wS.z  = fmaf(fT, t1a.z - t0a.z, t0a.z);
            wS.w  = fmaf(fT, t1a.w - t0a.w, t0a.w);
            w1v.x = fmaf(fT, t1b.x - t0b.x, t0b.x);
            w1v.y = fmaf(fT, t1b.y - t0b.y, t0b.y);
            w1v.z = fmaf(fT, t1b.z - t0b.z, t0b.z);
            w1v.w = fmaf(fT, t1b.w - t0b.w, t0b.w);
            w2v.x = fmaf(fT, t1c.x - t0c.x, t0c.x);
            w2v.y = fmaf(fT, t1c.y - t0c.y, t0c.y);
            w2v.z = fmaf(fT, t1c.z - t0c.z, t0c.z);
            w2v.w = fmaf(fT, t1c.w - t0c.w, t0c.w);

            accS.x += spa.x * wS.x;
            accS.y += spa.y * wS.y;
            accS.z += spa.z * wS.z;
            accS.w += spa.w * wS.w;

            float4 d1, d2;
            d1.x = spb.x * w1v.x; d1.y = spb.y * w1v.y;
            d1.z = spb.z * w1v.z; d1.w = spb.w * w1v.w;
            d2.x = spc.x * w2v.x; d2.y = spc.y * w2v.y;
            d2.z = spc.z * w2v.z; d2.w = spc.w * w2v.w;

            av0.x += d1.x * va.x + d2.x * uxT;
            av0.y += d1.x * va.y + d2.x * uyT;
            av0.z += d1.x * va.z + d2.x * uzT;
            av0.w += d1.y * va.w + d2.y * uxT;
            av1.x += d1.y * vb.x + d2.y * uyT;
            av1.y += d1.y * vb.y + d2.y * uzT;
            av1.z += d1.z * vb.z + d2.z * uxT;
            av1.w += d1.z * vb.w + d2.z * uyT;
            av2.x += d1.z * vc.x + d2.z * uzT;
            av2.y += d1.w * vc.y + d2.w * uxT;
            av2.z += d1.w * vc.z + d2.w * uyT;
            av2.w += d1.w * vc.w + d2.w * uzT;
        }
    }

    // store once
    ((float4*)(out + (size_t)dst * HH))[lane] = accS;
    float4* ov = (float4*)(out + (size_t)NN * HH + (size_t)dst * NOUT);
    ov[3 * lane + 0] = av0;
    ov[3 * lane + 1] = av1;
    ov[3 * lane + 2] = av2;
}

// ---------------------------------------------------------------------------
extern "C" void kernel_launch(void* const* d_in, const int* in_sizes, int n_in,
                              void* d_out, int out_size) {
    const float* s      = (const float*)d_in[0];
    const float* v      = (const float*)d_in[1];
    const float* pos    = (const float*)d_in[2];
    const float* rbf_c  = (const float*)d_in[3];
    const float* rbf_w  = (const float*)d_in[4];
    const float* phi_w1 = (const float*)d_in[5];
    const float* phi_b1 = (const float*)d_in[6];
    const float* phi_w2 = (const float*)d_in[7];
    const float* phi_b2 = (const float*)d_in[8];
    const float* w_w1   = (const float*)d_in[9];
    const float* w_b1   = (const float*)d_in[10];
    const float* w_w2   = (const float*)d_in[11];
    const float* w_b2   = (const float*)d_in[12];
    const int*   ei     = (const int*)d_in[13];
    float* out = (float*)d_out;

    // CSR build (by dst)
    zero_cnt_kernel<<<(NN + 256) / 256, 256>>>();
    hist_kernel<<<(EE + 255) / 256, 256>>>(ei);
    scan_kernel<<<1, 1024>>>();
    scatter_kernel<<<(EE + 255) / 256, 256>>>(ei);

    // distance->W table
    build_tab_kernel<<<NT / 8, 128>>>(rbf_c, rbf_w, w_w1, w_b1, w_w2, w_b2);

    // per-node scalar MLP (tf32 tensor cores)
    {
        size_t smem = MLP_SMEM_FLOATS * sizeof(float);
        cudaFuncSetAttribute(node_mlp_wmma,
                             cudaFuncAttributeMaxDynamicSharedMemorySize, (int)smem);
        node_mlp_wmma<<<(NN + 63) / 64, 256, smem>>>(s, phi_w1, phi_b1, phi_w2, phi_b2);
    }

    // edge accumulate (warp per dst, no atomics, init fused)
    accum_kernel<<<(NN * 32 + 255) / 256, 256>>>(pos, s, v, ei, out);
}

// round 6
// speedup vs baseline: 1.0024x; 1.0024x over previous
#include <cuda_runtime.h>
#include <math.h>
#include <mma.h>

using namespace nvcuda;

#define NN    50000
#define EE    400000
#define HH    128
#define NRBFN 20
#define NOUT  384          // 3*H
#define FCUT  8.0f
#define NT    4096         // distance table resolution

// Scratch (device globals: allocation-free rule)
__device__ float g_spn[NN * NOUT];              // per-node scalar-MLP output, 76.8 MB
__device__ float g_tab[NT * NOUT];              // W(d) table, 6.3 MB (L2-resident)
__device__ __align__(16) float g_scr[3][NN * HH]; // vector-message channel planes, 76.8 MB

__device__ __forceinline__ float silu_f(float x) {
    return x / (1.0f + __expf(-x));
}

__device__ __forceinline__ void red_add_v4(float* p, float a, float b, float c, float d) {
    asm volatile("red.global.add.v4.f32 [%0], {%1,%2,%3,%4};"
                 :: "l"(p), "f"(a), "f"(b), "f"(c), "f"(d) : "memory");
}

// ---------------------------------------------------------------------------
// Kernel 0: out_s = s ; scr = 0   (out_v fully overwritten by final kernel)
// ---------------------------------------------------------------------------
__global__ void init_kernel(const float* __restrict__ s, float* __restrict__ out) {
    int i = blockIdx.x * blockDim.x + threadIdx.x;       // float4 index
    const int nS4 = NN * HH / 4;                          // 1.6M
    const int nZ4 = 3 * NN * HH / 4;                      // 4.8M
    if (i < nS4) {
        ((float4*)out)[i] = ((const float4*)s)[i];
    } else if (i < nS4 + nZ4) {
        ((float4*)g_scr)[i - nS4] = make_float4(0.f, 0.f, 0.f, 0.f);
    }
}

// ---------------------------------------------------------------------------
// W(d) table. 8 rows per block, 128 threads.
// ---------------------------------------------------------------------------
__global__ void build_tab_kernel(const float* __restrict__ rbf_c,
                                 const float* __restrict__ rbf_w,
                                 const float* __restrict__ w1,   // [128,20]
                                 const float* __restrict__ b1,   // [128]
                                 const float* __restrict__ w2,   // [384,128]
                                 const float* __restrict__ b2) { // [384]
    __shared__ float feat_sm[8][NRBFN];
    __shared__ float g_sm[8][HH];
    const int tid  = threadIdx.x;        // 128
    const int row0 = blockIdx.x * 8;

    for (int idx = tid; idx < 8 * NRBFN; idx += 128) {
        int r = idx / NRBFN, i = idx % NRBFN;
        float d   = (row0 + r) * (FCUT / (float)(NT - 1));
        float x   = d / FCUT;
        float env = (x < 1.0f) ? 0.5f * (__cosf(3.14159265358979f * x) + 1.0f) : 0.0f;
        float df  = d - rbf_c[i];
        feat_sm[r][i] = __expf(-fabsf(rbf_w[i]) * df * df) * env;
    }
    __syncthreads();

    float wrow[NRBFN];
    #pragma unroll
    for (int i = 0; i < NRBFN; i++) wrow[i] = w1[tid * NRBFN + i];
    float bb = b1[tid];
    #pragma unroll
    for (int r = 0; r < 8; r++) {
        float a = bb;
        #pragma unroll
        for (int i = 0; i < NRBFN; i++) a += feat_sm[r][i] * wrow[i];
        g_sm[r][tid] = silu_f(a);
    }
    __syncthreads();

    float a0[8], a1[8], a2[8];
    #pragma unroll
    for (int r = 0; r < 8; r++) { a0[r] = 0.f; a1[r] = 0.f; a2[r] = 0.f; }
    const float* w2r0 = w2 + (tid)       * HH;
    const float* w2r1 = w2 + (tid + 128) * HH;
    const float* w2r2 = w2 + (tid + 256) * HH;
    for (int k = 0; k < HH; k++) {
        float x0 = w2r0[k], x1 = w2r1[k], x2 = w2r2[k];
        #pragma unroll
        for (int r = 0; r < 8; r++) {
            float h = g_sm[r][k];
            a0[r] += h * x0; a1[r] += h * x1; a2[r] += h * x2;
        }
    }
    float c0 = b2[tid], c1 = b2[tid + 128], c2 = b2[tid + 256];
    #pragma unroll
    for (int r = 0; r < 8; r++) {
        float* o = g_tab + (row0 + r) * NOUT;
        o[tid]       = a0[r] + c0;
        o[tid + 128] = a1[r] + c1;
        o[tid + 256] = a2[r] + c2;
    }
}

// ---------------------------------------------------------------------------
// Node scalar MLP, tf32 WMMA. 64 rows/block, 256 threads.
// Weights stay in L2 (reused by all blocks); smem only for activations: 88 KB.
// ---------------------------------------------------------------------------
#define MLP_SMEM_FLOATS (64*128 + 64*128 + 64*96)

__global__ void node_mlp_wmma(const float* __restrict__ s,
                              const float* __restrict__ w1,   // [128,128]
                              const float* __restrict__ b1,
                              const float* __restrict__ w2,   // [384,128]
                              const float* __restrict__ b2) {
    extern __shared__ float sm[];
    float* s_sm   = sm;                    // 8192
    float* h_sm   = sm + 8192;             // 8192
    float* out_sm = sm + 16384;            // 6144

    const int tid  = threadIdx.x;          // 256
    const int warp = tid >> 5;             // 8 warps
    const int n0   = blockIdx.x * 64;

    // load s tile (clamp OOB rows)
    {
        const float4* s4 = (const float4*)s;
        float4* d4 = (float4*)s_sm;
        for (int q = tid; q < 64 * 32; q += 256) {
            int r  = q >> 5;
            int gr = n0 + r; if (gr >= NN) gr = NN - 1;
            d4[q] = s4[gr * 32 + (q & 31)];
        }
    }
    __syncthreads();

    // ---- layer 1: h = s @ W1^T  (B fragments straight from L2) ----
    {
        const int mt    = warp >> 1;           // 0..3
        const int nhalf = warp & 1;            // 0..1
        wmma::fragment<wmma::accumulator, 16, 16, 8, float> c[4];
        #pragma unroll
        for (int j = 0; j < 4; j++) wmma::fill_fragment(c[j], 0.0f);
        for (int k = 0; k < HH; k += 8) {
            wmma::fragment<wmma::matrix_a, 16, 16, 8, wmma::precision::tf32, wmma::row_major> a;
            wmma::load_matrix_sync(a, s_sm + mt * 16 * 128 + k, 128);
            #pragma unroll
            for (int i = 0; i < a.num_elements; i++) a.x[i] = wmma::__float_to_tf32(a.x[i]);
            #pragma unroll
            for (int j = 0; j < 4; j++) {
                wmma::fragment<wmma::matrix_b, 16, 16, 8, wmma::precision::tf32, wmma::col_major> b;
                wmma::load_matrix_sync(b, w1 + (nhalf * 64 + j * 16) * 128 + k, 128);
                #pragma unroll
                for (int i = 0; i < b.num_elements; i++) b.x[i] = wmma::__float_to_tf32(b.x[i]);
                wmma::mma_sync(c[j], a, b, c[j]);
            }
        }
        #pragma unroll
        for (int j = 0; j < 4; j++)
            wmma::store_matrix_sync(h_sm + mt * 16 * 128 + (nhalf * 64 + j * 16), c[j], 128,
                                    wmma::mem_row_major);
    }
    __syncthreads();
    // bias + silu
    for (int i = tid; i < 64 * 128; i += 256)
        h_sm[i] = silu_f(h_sm[i] + b1[i & 127]);
    __syncthreads();

    // ---- layer 2: sp = h @ W2^T, 4 chunks of 96 output cols ----
    for (int chunk = 0; chunk < 4; chunk++) {
        const float* w2c = w2 + chunk * 96 * 128;
        const int mt = warp >> 1;
        const int nh = warp & 1;               // 3 n-tiles each
        wmma::fragment<wmma::accumulator, 16, 16, 8, float> c[3];
        #pragma unroll
        for (int j = 0; j < 3; j++) wmma::fill_fragment(c[j], 0.0f);
        for (int k = 0; k < HH; k += 8) {
            wmma::fragment<wmma::matrix_a, 16, 16, 8, wmma::precision::tf32, wmma::row_major> a;
            wmma::load_matrix_sync(a, h_sm + mt * 16 * 128 + k, 128);
            #pragma unroll
            for (int i = 0; i < a.num_elements; i++) a.x[i] = wmma::__float_to_tf32(a.x[i]);
            #pragma unroll
            for (int j = 0; j < 3; j++) {
                wmma::fragment<wmma::matrix_b, 16, 16, 8, wmma::precision::tf32, wmma::col_major> b;
                wmma::load_matrix_sync(b, w2c + (nh * 48 + j * 16) * 128 + k, 128);
                #pragma unroll
                for (int i = 0; i < b.num_elements; i++) b.x[i] = wmma::__float_to_tf32(b.x[i]);
                wmma::mma_sync(c[j], a, b, c[j]);
            }
        }
        #pragma unroll
        for (int j = 0; j < 3; j++)
            wmma::store_matrix_sync(out_sm + mt * 16 * 96 + (nh * 48 + j * 16), c[j], 96,
                                    wmma::mem_row_major);
        __syncthreads();

        for (int i = tid; i < 64 * 96; i += 256) {
            int r = i / 96, n = i - r * 96;
            int gr = n0 + r;
            if (gr < NN)
                g_spn[gr * NOUT + chunk * 96 + n] = out_sm[i] + b2[chunk * 96 + n];
        }
        __syncthreads();
    }
}

// ---------------------------------------------------------------------------
// Edge kernel: one warp per edge, v4 vector reductions, no read-modify races.
// s-part -> out directly; vector part -> 3 channel planes g_scr[c][dst][h].
// ---------------------------------------------------------------------------
__global__ void edge_kernel(const float* __restrict__ pos,
                            const float* __restrict__ v,
                            const int* __restrict__ ei,
                            float* __restrict__ out) {
    const int gw   = (blockIdx.x * blockDim.x + threadIdx.x) >> 5;
    const int lane = threadIdx.x & 31;
    if (gw >= EE) return;

    const int src = ei[gw];
    const int dst = ei[EE + gw];

    float rx = pos[dst * 3 + 0] - pos[src * 3 + 0];
    float ry = pos[dst * 3 + 1] - pos[src * 3 + 1];
    float rz = pos[dst * 3 + 2] - pos[src * 3 + 2];
    float d  = fmaxf(sqrtf(rx * rx + ry * ry + rz * rz), 1e-6f);
    float iv = 1.0f / d;
    float u[3] = { rx * iv, ry * iv, rz * iv };

    float t = fminf(d, FCUT) * ((float)(NT - 1) / FCUT);
    int   i0 = (int)t;
    if (i0 > NT - 2) i0 = NT - 2;
    float f = t - (float)i0;

    const float4* t0 = (const float4*)(g_tab + (size_t)i0 * NOUT);
    const float4* t1 = t0 + 96;
    const float4* sp = (const float4*)(g_spn + (size_t)src * NOUT);
    const float4* vr = (const float4*)(v + (size_t)src * NOUT);

    // lane owns h = 4*lane .. 4*lane+3
    float4 t0a = t0[lane], t0b = t0[32 + lane], t0c = t0[64 + lane];
    float4 t1a = t1[lane], t1b = t1[32 + lane], t1c = t1[64 + lane];
    float4 spa = sp[lane], spb = sp[32 + lane], spc = sp[64 + lane];
    float4 v4a = vr[3 * lane + 0];
    float4 v4b = vr[3 * lane + 1];
    float4 v4c = vr[3 * lane + 2];
    float vv[12] = { v4a.x, v4a.y, v4a.z, v4a.w,
                     v4b.x, v4b.y, v4b.z, v4b.w,
                     v4c.x, v4c.y, v4c.z, v4c.w };

    // lerped weights
    float wS[4]  = { fmaf(f, t1a.x - t0a.x, t0a.x), fmaf(f, t1a.y - t0a.y, t0a.y),
                     fmaf(f, t1a.z - t0a.z, t0a.z), fmaf(f, t1a.w - t0a.w, t0a.w) };
    float w1v[4] = { fmaf(f, t1b.x - t0b.x, t0b.x), fmaf(f, t1b.y - t0b.y, t0b.y),
                     fmaf(f, t1b.z - t0b.z, t0b.z), fmaf(f, t1b.w - t0b.w, t0b.w) };
    float w2v[4] = { fmaf(f, t1c.x - t0c.x, t0c.x), fmaf(f, t1c.y - t0c.y, t0c.y),
                     fmaf(f, t1c.z - t0c.z, t0c.z), fmaf(f, t1c.w - t0c.w, t0c.w) };
    float spv[4] = { spa.x, spa.y, spa.z, spa.w };
    float d1[4], d2[4];
    #pragma unroll
    for (int k = 0; k < 4; k++) {
        float sb = (k == 0 ? spb.x : k == 1 ? spb.y : k == 2 ? spb.z : spb.w);
        float sc = (k == 0 ? spc.x : k == 1 ? spc.y : k == 2 ? spc.z : spc.w);
        d1[k] = sb * w1v[k];
        d2[k] = sc * w2v[k];
    }

    // scalar channel: out_s[dst][4l..] += sp*wS
    red_add_v4(out + (size_t)dst * HH + 4 * lane,
               spv[0] * wS[0], spv[1] * wS[1], spv[2] * wS[2], spv[3] * wS[3]);

    // vector channels: scr[c][dst][4l+k] += d1[k]*v[h][c] + d2[k]*u[c]
    #pragma unroll
    for (int c = 0; c < 3; c++) {
        red_add_v4(&g_scr[c][(size_t)dst * HH + 4 * lane],
                   fmaf(d1[0], vv[0 + c], d2[0] * u[c]),
                   fmaf(d1[1], vv[3 + c], d2[1] * u[c]),
                   fmaf(d1[2], vv[6 + c], d2[2] * u[c]),
                   fmaf(d1[3], vv[9 + c], d2[3] * u[c]));
    }
}

// ---------------------------------------------------------------------------
// Final: out_v[dst][h][c] = v[dst][h][c] + scr[c][dst][h]. Block per dst.
// ---------------------------------------------------------------------------
__global__ void final_v_kernel(const float* __restrict__ v,
                               float* __restrict__ out) {
    __shared__ float sc[3][HH];
    const int dst = blockIdx.x;
    const int tid = threadIdx.x;          // 128
    #pragma unroll
    for (int c = 0; c < 3; c++) sc[c][tid] = g_scr[c][(size_t)dst * HH + tid];
    __syncthreads();

    const float4* v4 = (const float4*)(v + (size_t)dst * NOUT);
    float4* o4 = (float4*)(out + (size_t)NN * HH + (size_t)dst * NOUT);
    if (tid < 96) {
        float4 a = v4[tid];
        int j = 4 * tid;
        a.x += sc[(j    ) % 3][(j    ) / 3];
        a.y += sc[(j + 1) % 3][(j + 1) / 3];
        a.z += sc[(j + 2) % 3][(j + 2) / 3];
        a.w += sc[(j + 3) % 3][(j + 3) / 3];
        o4[tid] = a;
    }
}

// ---------------------------------------------------------------------------
extern "C" void kernel_launch(void* const* d_in, const int* in_sizes, int n_in,
                              void* d_out, int out_size) {
    const float* s      = (const float*)d_in[0];
    const float* v      = (const float*)d_in[1];
    const float* pos    = (const float*)d_in[2];
    const float* rbf_c  = (const float*)d_in[3];
    const float* rbf_w  = (const float*)d_in[4];
    const float* phi_w1 = (const float*)d_in[5];
    const float* phi_b1 = (const float*)d_in[6];
    const float* phi_w2 = (const float*)d_in[7];
    const float* phi_b2 = (const float*)d_in[8];
    const float* w_w1   = (const float*)d_in[9];
    const float* w_b1   = (const float*)d_in[10];
    const float* w_w2   = (const float*)d_in[11];
    const float* w_b2   = (const float*)d_in[12];
    const int*   ei     = (const int*)d_in[13];
    float* out = (float*)d_out;

    // 1) out_s = s ; scr = 0
    {
        int n4 = NN * HH / 4 + 3 * NN * HH / 4;
        init_kernel<<<(n4 + 255) / 256, 256>>>(s, out);
    }
    // 2) distance->W table
    build_tab_kernel<<<NT / 8, 128>>>(rbf_c, rbf_w, w_w1, w_b1, w_w2, w_b2);
    // 3) per-node scalar MLP (tf32 tensor cores)
    {
        size_t smem = MLP_SMEM_FLOATS * sizeof(float);
        cudaFuncSetAttribute(node_mlp_wmma,
                             cudaFuncAttributeMaxDynamicSharedMemorySize, (int)smem);
        node_mlp_wmma<<<(NN + 63) / 64, 256, smem>>>(s, phi_w1, phi_b1, phi_w2, phi_b2);
    }
    // 4) edges (warp per edge, v4 reductions)
    {
        long long threads = (long long)EE * 32;
        edge_kernel<<<(int)((threads + 255) / 256), 256>>>(pos, v, ei, out);
    }
    // 5) out_v = v + scr
    final_v_kernel<<<NN, 128>>>(v, out);
}

// round 7
// speedup vs baseline: 1.2632x; 1.2602x over previous
#include <cuda_runtime.h>
#include <cuda_fp16.h>
#include <math.h>
#include <mma.h>

using namespace nvcuda;

#define NN    50000
#define EE    400000
#define HH    128
#define NRBFN 20
#define NOUT  384          // 3*H
#define FCUT  8.0f
#define NT    4096         // distance table resolution

// Scratch (device globals: allocation-free rule)
__device__ float g_spn[NN * NOUT];                // per-node scalar-MLP output, 76.8 MB
__device__ float g_tab[NT * NOUT];                // W(d) table, 6.3 MB (L2-resident)
__device__ __align__(16) float g_scr[3][NN * HH]; // vector-message channel planes, 76.8 MB

__device__ __forceinline__ float silu_f(float x) {
    return x / (1.0f + __expf(-x));
}

__device__ __forceinline__ void red_add_v4(float* p, float a, float b, float c, float d) {
    asm volatile("red.global.add.v4.f32 [%0], {%1,%2,%3,%4};"
                 :: "l"(p), "f"(a), "f"(b), "f"(c), "f"(d) : "memory");
}

// ---------------------------------------------------------------------------
// Kernel 0: out_s = s ; scr = 0   (out_v fully overwritten by final kernel)
// ---------------------------------------------------------------------------
__global__ void init_kernel(const float* __restrict__ s, float* __restrict__ out) {
    int i = blockIdx.x * blockDim.x + threadIdx.x;       // float4 index
    const int nS4 = NN * HH / 4;                          // 1.6M
    const int nZ4 = 3 * NN * HH / 4;                      // 4.8M
    if (i < nS4) {
        ((float4*)out)[i] = ((const float4*)s)[i];
    } else if (i < nS4 + nZ4) {
        ((float4*)g_scr)[i - nS4] = make_float4(0.f, 0.f, 0.f, 0.f);
    }
}

// ---------------------------------------------------------------------------
// W(d) table. 8 rows per block, 128 threads.
// ---------------------------------------------------------------------------
__global__ void build_tab_kernel(const float* __restrict__ rbf_c,
                                 const float* __restrict__ rbf_w,
                                 const float* __restrict__ w1,   // [128,20]
                                 const float* __restrict__ b1,   // [128]
                                 const float* __restrict__ w2,   // [384,128]
                                 const float* __restrict__ b2) { // [384]
    __shared__ float feat_sm[8][NRBFN];
    __shared__ float g_sm[8][HH];
    const int tid  = threadIdx.x;        // 128
    const int row0 = blockIdx.x * 8;

    for (int idx = tid; idx < 8 * NRBFN; idx += 128) {
        int r = idx / NRBFN, i = idx % NRBFN;
        float d   = (row0 + r) * (FCUT / (float)(NT - 1));
        float x   = d / FCUT;
        float env = (x < 1.0f) ? 0.5f * (__cosf(3.14159265358979f * x) + 1.0f) : 0.0f;
        float df  = d - rbf_c[i];
        feat_sm[r][i] = __expf(-fabsf(rbf_w[i]) * df * df) * env;
    }
    __syncthreads();

    float wrow[NRBFN];
    #pragma unroll
    for (int i = 0; i < NRBFN; i++) wrow[i] = w1[tid * NRBFN + i];
    float bb = b1[tid];
    #pragma unroll
    for (int r = 0; r < 8; r++) {
        float a = bb;
        #pragma unroll
        for (int i = 0; i < NRBFN; i++) a += feat_sm[r][i] * wrow[i];
        g_sm[r][tid] = silu_f(a);
    }
    __syncthreads();

    float a0[8], a1[8], a2[8];
    #pragma unroll
    for (int r = 0; r < 8; r++) { a0[r] = 0.f; a1[r] = 0.f; a2[r] = 0.f; }
    const float* w2r0 = w2 + (tid)       * HH;
    const float* w2r1 = w2 + (tid + 128) * HH;
    const float* w2r2 = w2 + (tid + 256) * HH;
    for (int k = 0; k < HH; k++) {
        float x0 = w2r0[k], x1 = w2r1[k], x2 = w2r2[k];
        #pragma unroll
        for (int r = 0; r < 8; r++) {
            float h = g_sm[r][k];
            a0[r] += h * x0; a1[r] += h * x1; a2[r] += h * x2;
        }
    }
    float c0 = b2[tid], c1 = b2[tid + 128], c2 = b2[tid + 256];
    #pragma unroll
    for (int r = 0; r < 8; r++) {
        float* o = g_tab + (row0 + r) * NOUT;
        o[tid]       = a0[r] + c0;
        o[tid + 128] = a1[r] + c1;
        o[tid + 256] = a2[r] + c2;
    }
}

// ---------------------------------------------------------------------------
// Node scalar MLP, fp16 WMMA (m16n16k16), smem-staged weights.
// 64 rows/block, 256 threads (8 warps). smem = 96 KB -> 2 CTAs/SM.
//   s_h [64x128] half | h_h [64x128] half | w_h [128x128] half | acc [64x128] f32
// ---------------------------------------------------------------------------
#define MLP_SMEM_BYTES (64*128*2 + 64*128*2 + 128*128*2 + 64*128*4)

__global__ void node_mlp_fp16(const float* __restrict__ s,
                              const float* __restrict__ w1,   // [128,128]
                              const float* __restrict__ b1,
                              const float* __restrict__ w2,   // [384,128]
                              const float* __restrict__ b2) {
    extern __shared__ char smx[];
    half*  s_h = (half*)smx;                 // 8192 halfs
    half*  h_h = s_h + 64 * 128;             // 8192 halfs
    half*  w_h = h_h + 64 * 128;             // up to 16384 halfs
    float* acc = (float*)(w_h + 128 * 128);  // 8192 floats

    const int tid  = threadIdx.x;            // 256
    const int warp = tid >> 5;               // 8 warps
    const int mt   = warp & 3;               // m-tile 0..3
    const int nh   = warp >> 2;              // n-half 0..1
    const int n0   = blockIdx.x * 64;

    // load s tile -> half (clamp OOB rows)
    for (int q = tid; q < 64 * 32; q += 256) {
        int r  = q >> 5;
        int gr = n0 + r; if (gr >= NN) gr = NN - 1;
        float4 x = ((const float4*)s)[gr * 32 + (q & 31)];
        half2* d = (half2*)(s_h) + q * 2;
        d[0] = __floats2half2_rn(x.x, x.y);
        d[1] = __floats2half2_rn(x.z, x.w);
    }
    // load W1 -> half
    for (int q = tid; q < 128 * 32; q += 256) {
        float4 x = ((const float4*)w1)[q];
        half2* d = (half2*)(w_h) + q * 2;
        d[0] = __floats2half2_rn(x.x, x.y);
        d[1] = __floats2half2_rn(x.z, x.w);
    }
    __syncthreads();

    // ---- layer 1: h = s @ W1^T ----
    {
        wmma::fragment<wmma::accumulator, 16, 16, 16, float> c[4];
        #pragma unroll
        for (int j = 0; j < 4; j++) wmma::fill_fragment(c[j], 0.0f);
        for (int k = 0; k < HH; k += 16) {
            wmma::fragment<wmma::matrix_a, 16, 16, 16, half, wmma::row_major> a;
            wmma::load_matrix_sync(a, s_h + mt * 16 * 128 + k, 128);
            #pragma unroll
            for (int j = 0; j < 4; j++) {
                wmma::fragment<wmma::matrix_b, 16, 16, 16, half, wmma::col_major> b;
                wmma::load_matrix_sync(b, w_h + (nh * 64 + j * 16) * 128 + k, 128);
                wmma::mma_sync(c[j], a, b, c[j]);
            }
        }
        #pragma unroll
        for (int j = 0; j < 4; j++)
            wmma::store_matrix_sync(acc + mt * 16 * 128 + (nh * 64 + j * 16), c[j], 128,
                                    wmma::mem_row_major);
    }
    __syncthreads();
    // bias + silu -> half
    for (int i = tid; i < 64 * 128; i += 256)
        h_h[i] = __float2half(silu_f(acc[i] + b1[i & 127]));
    __syncthreads();

    // ---- layer 2: sp = h @ W2^T, 4 chunks of 96 output cols ----
    for (int chunk = 0; chunk < 4; chunk++) {
        // load W2 chunk [96 x 128] -> half
        for (int q = tid; q < 96 * 32; q += 256) {
            float4 x = ((const float4*)(w2 + chunk * 96 * 128))[q];
            half2* d = (half2*)(w_h) + q * 2;
            d[0] = __floats2half2_rn(x.x, x.y);
            d[1] = __floats2half2_rn(x.z, x.w);
        }
        __syncthreads();

        wmma::fragment<wmma::accumulator, 16, 16, 16, float> c[3];
        #pragma unroll
        for (int j = 0; j < 3; j++) wmma::fill_fragment(c[j], 0.0f);
        for (int k = 0; k < HH; k += 16) {
            wmma::fragment<wmma::matrix_a, 16, 16, 16, half, wmma::row_major> a;
            wmma::load_matrix_sync(a, h_h + mt * 16 * 128 + k, 128);
            #pragma unroll
            for (int j = 0; j < 3; j++) {
                wmma::fragment<wmma::matrix_b, 16, 16, 16, half, wmma::col_major> b;
                wmma::load_matrix_sync(b, w_h + (nh * 48 + j * 16) * 128 + k, 128);
                wmma::mma_sync(c[j], a, b, c[j]);
            }
        }
        #pragma unroll
        for (int j = 0; j < 3; j++)
            wmma::store_matrix_sync(acc + mt * 16 * 96 + (nh * 48 + j * 16), c[j], 96,
                                    wmma::mem_row_major);
        __syncthreads();

        // bias + write g_spn
        for (int i = tid; i < 64 * 96; i += 256) {
            int r = i / 96, n = i - r * 96;
            int gr = n0 + r;
            if (gr < NN)
                g_spn[gr * NOUT + chunk * 96 + n] = acc[i] + b2[chunk * 96 + n];
        }
        __syncthreads();
    }
}

// ---------------------------------------------------------------------------
// Edge kernel: one warp per edge, v4 vector reductions.
// s-part -> out directly; vector part -> 3 channel planes g_scr[c][dst][h].
// ---------------------------------------------------------------------------
__global__ void edge_kernel(const float* __restrict__ pos,
                            const float* __restrict__ v,
                            const int* __restrict__ ei,
                            float* __restrict__ out) {
    const int gw   = (blockIdx.x * blockDim.x + threadIdx.x) >> 5;
    const int lane = threadIdx.x & 31;
    if (gw >= EE) return;

    const int src = ei[gw];
    const int dst = ei[EE + gw];

    float rx = pos[dst * 3 + 0] - pos[src * 3 + 0];
    float ry = pos[dst * 3 + 1] - pos[src * 3 + 1];
    float rz = pos[dst * 3 + 2] - pos[src * 3 + 2];
    float d  = fmaxf(sqrtf(rx * rx + ry * ry + rz * rz), 1e-6f);
    float iv = 1.0f / d;
    float u[3] = { rx * iv, ry * iv, rz * iv };

    float t = fminf(d, FCUT) * ((float)(NT - 1) / FCUT);
    int   i0 = (int)t;
    if (i0 > NT - 2) i0 = NT - 2;
    float f = t - (float)i0;

    const float4* t0 = (const float4*)(g_tab + (size_t)i0 * NOUT);
    const float4* t1 = t0 + 96;
    const float4* sp = (const float4*)(g_spn + (size_t)src * NOUT);
    const float4* vr = (const float4*)(v + (size_t)src * NOUT);

    // lane owns h = 4*lane .. 4*lane+3
    float4 t0a = t0[lane], t0b = t0[32 + lane], t0c = t0[64 + lane];
    float4 t1a = t1[lane], t1b = t1[32 + lane], t1c = t1[64 + lane];
    float4 spa = sp[lane], spb = sp[32 + lane], spc = sp[64 + lane];
    float4 v4a = vr[3 * lane + 0];
    float4 v4b = vr[3 * lane + 1];
    float4 v4c = vr[3 * lane + 2];
    float vv[12] = { v4a.x, v4a.y, v4a.z, v4a.w,
                     v4b.x, v4b.y, v4b.z, v4b.w,
                     v4c.x, v4c.y, v4c.z, v4c.w };

    // lerped weights
    float wS[4]  = { fmaf(f, t1a.x - t0a.x, t0a.x), fmaf(f, t1a.y - t0a.y, t0a.y),
                     fmaf(f, t1a.z - t0a.z, t0a.z), fmaf(f, t1a.w - t0a.w, t0a.w) };
    float w1v[4] = { fmaf(f, t1b.x - t0b.x, t0b.x), fmaf(f, t1b.y - t0b.y, t0b.y),
                     fmaf(f, t1b.z - t0b.z, t0b.z), fmaf(f, t1b.w - t0b.w, t0b.w) };
    float w2v[4] = { fmaf(f, t1c.x - t0c.x, t0c.x), fmaf(f, t1c.y - t0c.y, t0c.y),
                     fmaf(f, t1c.z - t0c.z, t0c.z), fmaf(f, t1c.w - t0c.w, t0c.w) };
    float spv[4] = { spa.x, spa.y, spa.z, spa.w };
    float d1[4], d2[4];
    #pragma unroll
    for (int k = 0; k < 4; k++) {
        float sb = (k == 0 ? spb.x : k == 1 ? spb.y : k == 2 ? spb.z : spb.w);
        float sc = (k == 0 ? spc.x : k == 1 ? spc.y : k == 2 ? spc.z : spc.w);
        d1[k] = sb * w1v[k];
        d2[k] = sc * w2v[k];
    }

    // scalar channel: out_s[dst][4l..] += sp*wS
    red_add_v4(out + (size_t)dst * HH + 4 * lane,
               spv[0] * wS[0], spv[1] * wS[1], spv[2] * wS[2], spv[3] * wS[3]);

    // vector channels: scr[c][dst][4l+k] += d1[k]*v[h][c] + d2[k]*u[c]
    #pragma unroll
    for (int c = 0; c < 3; c++) {
        red_add_v4(&g_scr[c][(size_t)dst * HH + 4 * lane],
                   fmaf(d1[0], vv[0 + c], d2[0] * u[c]),
                   fmaf(d1[1], vv[3 + c], d2[1] * u[c]),
                   fmaf(d1[2], vv[6 + c], d2[2] * u[c]),
                   fmaf(d1[3], vv[9 + c], d2[3] * u[c]));
    }
}

// ---------------------------------------------------------------------------
// Final: out_v[dst][h][c] = v[dst][h][c] + scr[c][dst][h]. Block per dst.
// ---------------------------------------------------------------------------
__global__ void final_v_kernel(const float* __restrict__ v,
                               float* __restrict__ out) {
    __shared__ float sc[3][HH];
    const int dst = blockIdx.x;
    const int tid = threadIdx.x;          // 128
    #pragma unroll
    for (int c = 0; c < 3; c++) sc[c][tid] = g_scr[c][(size_t)dst * HH + tid];
    __syncthreads();

    const float4* v4 = (const float4*)(v + (size_t)dst * NOUT);
    float4* o4 = (float4*)(out + (size_t)NN * HH + (size_t)dst * NOUT);
    if (tid < 96) {
        float4 a = v4[tid];
        int j = 4 * tid;
        a.x += sc[(j    ) % 3][(j    ) / 3];
        a.y += sc[(j + 1) % 3][(j + 1) / 3];
        a.z += sc[(j + 2) % 3][(j + 2) / 3];
        a.w += sc[(j + 3) % 3][(j + 3) / 3];
        o4[tid] = a;
    }
}

// ---------------------------------------------------------------------------
extern "C" void kernel_launch(void* const* d_in, const int* in_sizes, int n_in,
                              void* d_out, int out_size) {
    const float* s      = (const float*)d_in[0];
    const float* v      = (const float*)d_in[1];
    const float* pos    = (const float*)d_in[2];
    const float* rbf_c  = (const float*)d_in[3];
    const float* rbf_w  = (const float*)d_in[4];
    const float* phi_w1 = (const float*)d_in[5];
    const float* phi_b1 = (const float*)d_in[6];
    const float* phi_w2 = (const float*)d_in[7];
    const float* phi_b2 = (const float*)d_in[8];
    const float* w_w1   = (const float*)d_in[9];
    const float* w_b1   = (const float*)d_in[10];
    const float* w_w2   = (const float*)d_in[11];
    const float* w_b2   = (const float*)d_in[12];
    const int*   ei     = (const int*)d_in[13];
    float* out = (float*)d_out;

    // 1) out_s = s ; scr = 0
    {
        int n4 = NN * HH / 4 + 3 * NN * HH / 4;
        init_kernel<<<(n4 + 255) / 256, 256>>>(s, out);
    }
    // 2) distance->W table
    build_tab_kernel<<<NT / 8, 128>>>(rbf_c, rbf_w, w_w1, w_b1, w_w2, w_b2);
    // 3) per-node scalar MLP (fp16 tensor cores, smem-staged weights)
    {
        cudaFuncSetAttribute(node_mlp_fp16,
                             cudaFuncAttributeMaxDynamicSharedMemorySize, MLP_SMEM_BYTES);
        node_mlp_fp16<<<(NN + 63) / 64, 256, MLP_SMEM_BYTES>>>(s, phi_w1, phi_b1,
                                                               phi_w2, phi_b2);
    }
    // 4) edges (warp per edge, v4 reductions)
    {
        long long threads = (long long)EE * 32;
        edge_kernel<<<(int)((threads + 255) / 256), 256>>>(pos, v, ei, out);
    }
    // 5) out_v = v + scr
    final_v_kernel<<<NN, 128>>>(v, out);
}

// round 9
// speedup vs baseline: 1.8000x; 1.4249x over previous
#include <cuda_runtime.h>
#include <cuda_fp16.h>
#include <math.h>
#include <mma.h>

using namespace nvcuda;

#define NN    50000
#define EE    400000
#define HH    128
#define NRBFN 20
#define NOUT  384          // 3*H
#define FCUT  8.0f
#define NT    4096         // distance table resolution

#define NROWPAD 50048      // NN rounded up to 64
#define NTILES  782        // NROWPAD / 64
#define LDH     136        // padded half row (128+8): <=2-way bank conflicts
#define LDF     132        // padded float row

// Scratch (device globals: allocation-free rule)
__device__ float g_spn[NROWPAD * NOUT];           // layer-2 GEMM output (no bias), 76.9 MB
__device__ float g_tab[NT * NOUT];                // W(d) table, 6.3 MB (L2-resident)
__device__ __align__(16) float g_scr[3][NN * HH]; // vector-message channel planes, 76.8 MB

__device__ __forceinline__ float silu_f(float x) {
    return x / (1.0f + __expf(-x));
}

__device__ __forceinline__ void red_add_v4(float* p, float a, float b, float c, float d) {
    asm volatile("red.global.add.v4.f32 [%0], {%1,%2,%3,%4};"
                 :: "l"(p), "f"(a), "f"(b), "f"(c), "f"(d) : "memory");
}

// ---------------------------------------------------------------------------
// Kernel 0: out_s = s ; scr = 0
// ---------------------------------------------------------------------------
__global__ void init_kernel(const float* __restrict__ s, float* __restrict__ out) {
    int i = blockIdx.x * blockDim.x + threadIdx.x;       // float4 index
    const int nS4 = NN * HH / 4;
    const int nZ4 = 3 * NN * HH / 4;
    if (i < nS4) {
        ((float4*)out)[i] = ((const float4*)s)[i];
    } else if (i < nS4 + nZ4) {
        ((float4*)g_scr)[i - nS4] = make_float4(0.f, 0.f, 0.f, 0.f);
    }
}

// ---------------------------------------------------------------------------
// W(d) table. 8 rows per block, 128 threads. float4 W2 reads.
// ---------------------------------------------------------------------------
__global__ void build_tab_kernel(const float* __restrict__ rbf_c,
                                 const float* __restrict__ rbf_w,
                                 const float* __restrict__ w1,   // [128,20]
                                 const float* __restrict__ b1,   // [128]
                                 const float* __restrict__ w2,   // [384,128]
                                 const float* __restrict__ b2) { // [384]
    __shared__ float feat_sm[8][NRBFN];
    __shared__ float g_sm[8][HH];
    const int tid  = threadIdx.x;        // 128
    const int row0 = blockIdx.x * 8;

    for (int idx = tid; idx < 8 * NRBFN; idx += 128) {
        int r = idx / NRBFN, i = idx % NRBFN;
        float d   = (row0 + r) * (FCUT / (float)(NT - 1));
        float x   = d / FCUT;
        float env = (x < 1.0f) ? 0.5f * (__cosf(3.14159265358979f * x) + 1.0f) : 0.0f;
        float df  = d - rbf_c[i];
        feat_sm[r][i] = __expf(-fabsf(rbf_w[i]) * df * df) * env;
    }
    __syncthreads();

    float wrow[NRBFN];
    #pragma unroll
    for (int i = 0; i < NRBFN; i++) wrow[i] = w1[tid * NRBFN + i];
    float bb = b1[tid];
    #pragma unroll
    for (int r = 0; r < 8; r++) {
        float a = bb;
        #pragma unroll
        for (int i = 0; i < NRBFN; i++) a += feat_sm[r][i] * wrow[i];
        g_sm[r][tid] = silu_f(a);
    }
    __syncthreads();

    float a0[8], a1[8], a2[8];
    #pragma unroll
    for (int r = 0; r < 8; r++) { a0[r] = 0.f; a1[r] = 0.f; a2[r] = 0.f; }
    const float4* w2r0 = (const float4*)(w2 + (tid)       * HH);
    const float4* w2r1 = (const float4*)(w2 + (tid + 128) * HH);
    const float4* w2r2 = (const float4*)(w2 + (tid + 256) * HH);
    for (int k4 = 0; k4 < HH / 4; k4++) {
        float4 x0 = w2r0[k4], x1 = w2r1[k4], x2 = w2r2[k4];
        #pragma unroll
        for (int r = 0; r < 8; r++) {
            const float* gr = &g_sm[r][k4 * 4];
            float h0 = gr[0], h1 = gr[1], h2 = gr[2], h3 = gr[3];
            a0[r] += h0 * x0.x + h1 * x0.y + h2 * x0.z + h3 * x0.w;
            a1[r] += h0 * x1.x + h1 * x1.y + h2 * x1.z + h3 * x1.w;
            a2[r] += h0 * x2.x + h1 * x2.y + h2 * x2.z + h3 * x2.w;
        }
    }
    float c0 = b2[tid], c1 = b2[tid + 128], c2 = b2[tid + 256];
    #pragma unroll
    for (int r = 0; r < 8; r++) {
        float* o = g_tab + (row0 + r) * NOUT;
        o[tid]       = a0[r] + c0;
        o[tid + 128] = a1[r] + c1;
        o[tid + 256] = a2[r] + c2;
    }
}

// ---------------------------------------------------------------------------
// Node scalar MLP: persistent fp16 WMMA GEMM.
// grid=148, 512 threads (16 warps), __launch_bounds__(512,1) caps regs at 128.
// Weights staged ONCE in padded smem. Per 64-row tile: layer1 -> silu ->
// layer2 stored DIRECTLY to g_spn (bias b2 folded into edge kernel).
// smem: w1_h[128][136] | w2_h[384][136] | s_h[64][136] | h_h[64][136] | acc[64][132]
// ---------------------------------------------------------------------------
#define MLP_SMEM_BYTES (128*LDH*2 + 384*LDH*2 + 64*LDH*2 + 64*LDH*2 + 64*LDF*4)

__global__ void __launch_bounds__(512, 1)
node_mlp_fp16(const float* __restrict__ s,
              const float* __restrict__ w1,   // [128,128]
              const float* __restrict__ b1,
              const float* __restrict__ w2) { // [384,128]
    extern __shared__ char smx[];
    half*  w1_h = (half*)smx;                    // 128*136
    half*  w2_h = w1_h + 128 * LDH;              // 384*136
    half*  s_h  = w2_h + 384 * LDH;              // 64*136
    half*  h_h  = s_h  + 64 * LDH;               // 64*136
    float* acc  = (float*)(h_h + 64 * LDH);      // 64*132

    const int tid  = threadIdx.x;                // 512
    const int warp = tid >> 5;                   // 16 warps

    // ---- stage weights once ----
    for (int q = tid; q < 128 * 32; q += 512) {  // W1: rows of 32 float4
        int r = q >> 5, c4 = q & 31;
        float4 x = ((const float4*)w1)[q];
        half2* d = (half2*)(w1_h + r * LDH + c4 * 4);
        d[0] = __floats2half2_rn(x.x, x.y);
        d[1] = __floats2half2_rn(x.z, x.w);
    }
    for (int q = tid; q < 384 * 32; q += 512) {  // W2
        int r = q >> 5, c4 = q & 31;
        float4 x = ((const float4*)w2)[q];
        half2* d = (half2*)(w2_h + r * LDH + c4 * 4);
        d[0] = __floats2half2_rn(x.x, x.y);
        d[1] = __floats2half2_rn(x.z, x.w);
    }
    __syncthreads();

    for (int t = blockIdx.x; t < NTILES; t += gridDim.x) {
        const int n0 = t * 64;

        // load s tile -> half, padded (clamp OOB rows)
        for (int q = tid; q < 64 * 32; q += 512) {
            int r  = q >> 5, c4 = q & 31;
            int gr = n0 + r; if (gr >= NN) gr = NN - 1;
            float4 x = ((const float4*)s)[gr * 32 + c4];
            half2* d = (half2*)(s_h + r * LDH + c4 * 4);
            d[0] = __floats2half2_rn(x.x, x.y);
            d[1] = __floats2half2_rn(x.z, x.w);
        }
        __syncthreads();

        // ---- layer 1: acc = s @ W1^T  (32 warp-tiles: 4m x 8n, 2 per warp) ----
        #pragma unroll 1
        for (int rep = 0; rep < 2; rep++) {
            int tt = warp + rep * 16;            // 0..31
            int mt = tt >> 3, nt = tt & 7;
            wmma::fragment<wmma::accumulator, 16, 16, 16, float> c;
            wmma::fill_fragment(c, 0.0f);
            for (int k = 0; k < HH; k += 16) {
                wmma::fragment<wmma::matrix_a, 16, 16, 16, half, wmma::row_major> a;
                wmma::fragment<wmma::matrix_b, 16, 16, 16, half, wmma::col_major> b;
                wmma::load_matrix_sync(a, s_h + mt * 16 * LDH + k, LDH);
                wmma::load_matrix_sync(b, w1_h + nt * 16 * LDH + k, LDH);
                wmma::mma_sync(c, a, b, c);
            }
            wmma::store_matrix_sync(acc + mt * 16 * LDF + nt * 16, c, LDF,
                                    wmma::mem_row_major);
        }
        __syncthreads();

        // bias + silu -> h_h
        for (int i = tid; i < 64 * 128; i += 512) {
            int r = i >> 7, k = i & 127;
            h_h[r * LDH + k] = __float2half(silu_f(acc[r * LDF + k] + b1[k]));
        }
        __syncthreads();

        // ---- layer 2: g_spn = h @ W2^T  (96 warp-tiles: 4m x 24n, 6 per warp) ----
        #pragma unroll 1
        for (int rep = 0; rep < 6; rep++) {
            int tt = warp + rep * 16;            // 0..95
            int mt = tt / 24, nt = tt % 24;
            wmma::fragment<wmma::accumulator, 16, 16, 16, float> c;
            wmma::fill_fragment(c, 0.0f);
            for (int k = 0; k < HH; k += 16) {
                wmma::fragment<wmma::matrix_a, 16, 16, 16, half, wmma::row_major> a;
                wmma::fragment<wmma::matrix_b, 16, 16, 16, half, wmma::col_major> b;
                wmma::load_matrix_sync(a, h_h + mt * 16 * LDH + k, LDH);
                wmma::load_matrix_sync(b, w2_h + nt * 16 * LDH + k, LDH);
                wmma::mma_sync(c, a, b, c);
            }
            wmma::store_matrix_sync(g_spn + (size_t)(n0 + mt * 16) * NOUT + nt * 16,
                                    c, NOUT, wmma::mem_row_major);
        }
        __syncthreads();
    }
}

// ---------------------------------------------------------------------------
// Edge kernel: one warp per edge, v4 vector reductions. b2 added here.
// ---------------------------------------------------------------------------
__global__ void edge_kernel(const float* __restrict__ pos,
                            const float* __restrict__ v,
                            const int* __restrict__ ei,
                            const float* __restrict__ b2,
                            float* __restrict__ out) {
    const int gw   = (blockIdx.x * blockDim.x + threadIdx.x) >> 5;
    const int lane = threadIdx.x & 31;
    if (gw >= EE) return;

    const int src = ei[gw];
    const int dst = ei[EE + gw];

    float rx = pos[dst * 3 + 0] - pos[src * 3 + 0];
    float ry = pos[dst * 3 + 1] - pos[src * 3 + 1];
    float rz = pos[dst * 3 + 2] - pos[src * 3 + 2];
    float d  = fmaxf(sqrtf(rx * rx + ry * ry + rz * rz), 1e-6f);
    float iv = 1.0f / d;
    float u[3] = { rx * iv, ry * iv, rz * iv };

    float t = fminf(d, FCUT) * ((float)(NT - 1) / FCUT);
    int   i0 = (int)t;
    if (i0 > NT - 2) i0 = NT - 2;
    float f = t - (float)i0;

    const float4* t0 = (const float4*)(g_tab + (size_t)i0 * NOUT);
    const float4* t1 = t0 + 96;
    const float4* sp = (const float4*)(g_spn + (size_t)src * NOUT);
    const float4* vr = (const float4*)(v + (size_t)src * NOUT);
    const float4* b2v = (const float4*)b2;

    float4 t0a = t0[lane], t0b = t0[32 + lane], t0c = t0[64 + lane];
    float4 t1a = t1[lane], t1b = t1[32 + lane], t1c = t1[64 + lane];
    float4 spa = sp[lane], spb = sp[32 + lane], spc = sp[64 + lane];
    float4 ba = b2v[lane], bb = b2v[32 + lane], bc = b2v[64 + lane];
    spa.x += ba.x; spa.y += ba.y; spa.z += ba.z; spa.w += ba.w;
    spb.x += bb.x; spb.y += bb.y; spb.z += bb.z; spb.w += bb.w;
    spc.x += bc.x; spc.y += bc.y; spc.z += bc.z; spc.w += bc.w;

    float4 v4a = vr[3 * lane + 0];
    float4 v4b = vr[3 * lane + 1];
    float4 v4c = vr[3 * lane + 2];
    float vv[12] = { v4a.x, v4a.y, v4a.z, v4a.w,
                     v4b.x, v4b.y, v4b.z, v4b.w,
                     v4c.x, v4c.y, v4c.z, v4c.w };

    float wS[4]  = { fmaf(f, t1a.x - t0a.x, t0a.x), fmaf(f, t1a.y - t0a.y, t0a.y),
                     fmaf(f, t1a.z - t0a.z, t0a.z), fmaf(f, t1a.w - t0a.w, t0a.w) };
    float w1v[4] = { fmaf(f, t1b.x - t0b.x, t0b.x), fmaf(f, t1b.y - t0b.y, t0b.y),
                     fmaf(f, t1b.z - t0b.z, t0b.z), fmaf(f, t1b.w - t0b.w, t0b.w) };
    float w2v[4] = { fmaf(f, t1c.x - t0c.x, t0c.x), fmaf(f, t1c.y - t0c.y, t0c.y),
                     fmaf(f, t1c.z - t0c.z, t0c.z), fmaf(f, t1c.w - t0c.w, t0c.w) };
    float spv[4] = { spa.x, spa.y, spa.z, spa.w };
    float d1[4], d2[4];
    #pragma unroll
    for (int k = 0; k < 4; k++) {
        float sb = (k == 0 ? spb.x : k == 1 ? spb.y : k == 2 ? spb.z : spb.w);
        float sc = (k == 0 ? spc.x : k == 1 ? spc.y : k == 2 ? spc.z : spc.w);
        d1[k] = sb * w1v[k];
        d2[k] = sc * w2v[k];
    }

    red_add_v4(out + (size_t)dst * HH + 4 * lane,
               spv[0] * wS[0], spv[1] * wS[1], spv[2] * wS[2], spv[3] * wS[3]);

    #pragma unroll
    for (int c = 0; c < 3; c++) {
        red_add_v4(&g_scr[c][(size_t)dst * HH + 4 * lane],
                   fmaf(d1[0], vv[0 + c], d2[0] * u[c]),
                   fmaf(d1[1], vv[3 + c], d2[1] * u[c]),
                   fmaf(d1[2], vv[6 + c], d2[2] * u[c]),
                   fmaf(d1[3], vv[9 + c], d2[3] * u[c]));
    }
}

// ---------------------------------------------------------------------------
// Final: out_v[dst][h][c] = v[dst][h][c] + scr[c][dst][h]. Block per dst.
// ---------------------------------------------------------------------------
__global__ void final_v_kernel(const float* __restrict__ v,
                               float* __restrict__ out) {
    __shared__ float sc[3][HH];
    const int dst = blockIdx.x;
    const int tid = threadIdx.x;          // 128
    #pragma unroll
    for (int c = 0; c < 3; c++) sc[c][tid] = g_scr[c][(size_t)dst * HH + tid];
    __syncthreads();

    const float4* v4 = (const float4*)(v + (size_t)dst * NOUT);
    float4* o4 = (float4*)(out + (size_t)NN * HH + (size_t)dst * NOUT);
    if (tid < 96) {
        float4 a = v4[tid];
        int j = 4 * tid;
        a.x += sc[(j    ) % 3][(j    ) / 3];
        a.y += sc[(j + 1) % 3][(j + 1) / 3];
        a.z += sc[(j + 2) % 3][(j + 2) / 3];
        a.w += sc[(j + 3) % 3][(j + 3) / 3];
        o4[tid] = a;
    }
}

// ---------------------------------------------------------------------------
extern "C" void kernel_launch(void* const* d_in, const int* in_sizes, int n_in,
                              void* d_out, int out_size) {
    const float* s      = (const float*)d_in[0];
    const float* v      = (const float*)d_in[1];
    const float* pos    = (const float*)d_in[2];
    const float* rbf_c  = (const float*)d_in[3];
    const float* rbf_w  = (const float*)d_in[4];
    const float* phi_w1 = (const float*)d_in[5];
    const float* phi_b1 = (const float*)d_in[6];
    const float* phi_w2 = (const float*)d_in[7];
    const float* phi_b2 = (const float*)d_in[8];
    const float* w_w1   = (const float*)d_in[9];
    const float* w_b1   = (const float*)d_in[10];
    const float* w_w2   = (const float*)d_in[11];
    const float* w_b2   = (const float*)d_in[12];
    const int*   ei     = (const int*)d_in[13];
    float* out = (float*)d_out;

    // 1) out_s = s ; scr = 0
    {
        int n4 = NN * HH / 4 + 3 * NN * HH / 4;
        init_kernel<<<(n4 + 255) / 256, 256>>>(s, out);
    }
    // 2) distance->W table
    build_tab_kernel<<<NT / 8, 128>>>(rbf_c, rbf_w, w_w1, w_b1, w_w2, w_b2);
    // 3) per-node scalar MLP (persistent fp16 WMMA, padded smem)
    {
        cudaFuncSetAttribute(node_mlp_fp16,
                             cudaFuncAttributeMaxDynamicSharedMemorySize, MLP_SMEM_BYTES);
        node_mlp_fp16<<<148, 512, MLP_SMEM_BYTES>>>(s, phi_w1, phi_b1, phi_w2);
    }
    // 4) edges (warp per edge, v4 reductions, +b2)
    {
        long long threads = (long long)EE * 32;
        edge_kernel<<<(int)((threads + 255) / 256), 256>>>(pos, v, ei, phi_b2, out);
    }
    // 5) out_v = v + scr
    final_v_kernel<<<NN, 128>>>(v, out);
}